// round 11
// baseline (speedup 1.0000x reference)
#include <cuda_runtime.h>
#include <cuda_fp16.h>
#include <math.h>
#include <stdint.h>

#define BATCH 4
#define NSP   4096      // H*W spatial tokens
#define DM    512
#define NH    8
#define DH    64
#define NG    256       // groups (16x16)
#define JL    8         // latents per group
#define NLAT  2048      // NG*JL
#define EPSV  1e-5f

// ---------------- helpers ----------------
// fp16-accumulator MMA: D(f16x4 in 2 regs) = A*B + D
#define MMA_F16H(d, a, b0, b1) \
    asm volatile("mma.sync.aligned.m16n8k16.row.col.f16.f16.f16.f16 " \
        "{%0,%1}, {%2,%3,%4,%5}, {%6,%7}, {%0,%1};" \
        : "+r"((d)[0]), "+r"((d)[1]) \
        : "r"((a)[0]), "r"((a)[1]), "r"((a)[2]), "r"((a)[3]), \
          "r"(b0), "r"(b1))

#define LDMX4(r0, r1, r2, r3, addr) \
    asm volatile("ldmatrix.sync.aligned.m8n8.x4.shared.b16 {%0,%1,%2,%3}, [%4];" \
        : "=r"(r0), "=r"(r1), "=r"(r2), "=r"(r3) : "r"(addr))

__device__ __forceinline__ void cp_async16(uint32_t smem_addr, const void* gptr) {
    asm volatile("cp.async.cg.shared.global [%0], [%1], 16;"
        :: "r"(smem_addr), "l"(gptr));
}
#define CP_COMMIT()  asm volatile("cp.async.commit_group;" ::: "memory")
#define CP_WAIT(N)   asm volatile("cp.async.wait_group %0;" :: "n"(N) : "memory")

__device__ __forceinline__ uint32_t smem_u32(const void* p) {
    uint32_t a;
    asm("{ .reg .u64 t; cvta.to.shared.u64 t, %1; cvt.u32.u64 %0, t; }" : "=r"(a) : "l"(p));
    return a;
}

// ---------------- scratch (device globals; no allocs allowed) ----------------
__device__ float  g_mod[BATCH * 1024];
__device__ float  g_lat[BATCH * JL * DM];       // modulated latents (residual, fp32)
__device__ float  g_qh [BATCH * JL * DM];       // q heads post head-LN (fp32)
__device__ __half g_kvn[BATCH * NSP * DM];      // LN(spatial), fp16
__device__ __half g_k  [BATCH * NSP * DM];      // k proj, head-LN fused, fp16
__device__ __half g_v  [BATCH * NSP * DM];      // v proj, fp16
__device__ __half g_ao [BATCH * NLAT * DM];     // attention out, fp16
__device__ __half g_wk [DM * DM];               // fp16 weights
__device__ __half g_wv [DM * DM];
__device__ __half g_wo [DM * DM];

// -------- 0) prelude: weight fp16 conversion (blocks 0-767) + mod GEMV (768-895) --------
__global__ void prelude_kernel(const float* __restrict__ s0, __half* __restrict__ d0,
                               const float* __restrict__ s1, __half* __restrict__ d1,
                               const float* __restrict__ s2, __half* __restrict__ d2,
                               const float* __restrict__ cond,
                               const float* __restrict__ Wad,
                               const float* __restrict__ bad) {
    int blk = blockIdx.x;
    int t = threadIdx.x;
    if (blk < 768) {
        int which = blk >> 8;
        int i = (blk & 255) * 256 + t;       // float4 index
        const float* src = (which == 0) ? s0 : (which == 1) ? s1 : s2;
        __half*      dst = (which == 0) ? d0 : (which == 1) ? d1 : d2;
        float4 v = ((const float4*)src)[i];
        ((__half2*)dst)[2 * i]     = __floats2half2_rn(v.x, v.y);
        ((__half2*)dst)[2 * i + 1] = __floats2half2_rn(v.z, v.w);
    } else {
        int o = (blk - 768) * 32 + (t >> 3);  // 0..4095
        int sub = t & 7;
        int b = o >> 10, oo = o & 1023;
        const float4* w  = (const float4*)(Wad + (size_t)oo * 512);
        const float4* cn = (const float4*)(cond + (size_t)b * 512);
        float acc = 0.f;
        #pragma unroll
        for (int k = sub * 16; k < sub * 16 + 16; k++) {
            float4 wv = w[k], cv = cn[k];
            acc += wv.x * cv.x + wv.y * cv.y + wv.z * cv.z + wv.w * cv.w;
        }
        acc += __shfl_xor_sync(0xffffffffu, acc, 1);
        acc += __shfl_xor_sync(0xffffffffu, acc, 2);
        acc += __shfl_xor_sync(0xffffffffu, acc, 4);
        if (sub == 0) g_mod[b * 1024 + oo] = acc + bad[oo];
    }
}

// ------ 2) latents: modulate -> LN -> @Wq^T+bq -> head-LN  (32 rows) ------
__global__ void latq_kernel(const float* __restrict__ lt, const float* __restrict__ lp,
                            const float* __restrict__ Wq, const float* __restrict__ bq,
                            const float* __restrict__ nqg, const float* __restrict__ nqb,
                            const float* __restrict__ qng, const float* __restrict__ qnb) {
    __shared__ float r1[512], r2[512], sval[512];
    int b = blockIdx.x >> 3, j = blockIdx.x & 7;
    int t = threadIdx.x;

    float base  = lt[j * DM + t] + lp[j * DM + t];
    float shift = g_mod[b * 1024 + t];
    float scale = g_mod[b * 1024 + 512 + t];
    float lat   = base * (1.f + scale) + shift;
    g_lat[(size_t)blockIdx.x * DM + t] = lat;

    r1[t] = lat; r2[t] = lat * lat;
    __syncthreads();
    for (int s = 256; s >= 1; s >>= 1) {
        if (t < s) { r1[t] += r1[t + s]; r2[t] += r2[t + s]; }
        __syncthreads();
    }
    float mu  = r1[0] * (1.f / 512.f);
    float var = r2[0] * (1.f / 512.f) - mu * mu;
    float rs  = rsqrtf(var + EPSV);
    sval[t] = (lat - mu) * rs * nqg[t] + nqb[t];
    __syncthreads();

    float acc = bq[t];
    const float4* w  = (const float4*)(Wq + (size_t)t * DM);
    const float4* s4 = (const float4*)sval;
    #pragma unroll 8
    for (int k = 0; k < 128; k++) {
        float4 wv = w[k], sv = s4[k];
        acc += wv.x * sv.x + wv.y * sv.y + wv.z * sv.z + wv.w * sv.w;
    }
    __syncthreads();

    r1[t] = acc; r2[t] = acc * acc;
    __syncthreads();
    for (int s = 32; s >= 1; s >>= 1) {
        if ((t & 63) < s) { r1[t] += r1[t + s]; r2[t] += r2[t + s]; }
        __syncthreads();
    }
    int hb = t & ~63, l = t & 63;
    float mu2  = r1[hb] * (1.f / 64.f);
    float var2 = r2[hb] * (1.f / 64.f) - mu2 * mu2;
    g_qh[(size_t)blockIdx.x * DM + t] =
        (acc - mu2) * rsqrtf(var2 + EPSV) * qng[l] + qnb[l];
}

// ------ 3) kv = LN(spatial), fp16 out; warp-per-row, shuffle-only (2048 blocks) ------
__global__ void __launch_bounds__(256) lnkv_kernel(const float* __restrict__ sp,
                                                   const float* __restrict__ gg,
                                                   const float* __restrict__ bb) {
    int warp = threadIdx.x >> 5, lane = threadIdx.x & 31;
    int row = blockIdx.x * 8 + warp;
    const float4* x4 = (const float4*)(sp + (size_t)row * DM);
    float4 xv[4];
    float s = 0.f, s2 = 0.f;
    #pragma unroll
    for (int i = 0; i < 4; i++) {
        float4 x = x4[lane + 32 * i];
        xv[i] = x;
        s  += x.x + x.y + x.z + x.w;
        s2 += x.x * x.x + x.y * x.y + x.z * x.z + x.w * x.w;
    }
    #pragma unroll
    for (int o = 16; o >= 1; o >>= 1) {
        s  += __shfl_xor_sync(0xffffffffu, s,  o);
        s2 += __shfl_xor_sync(0xffffffffu, s2, o);
    }
    float mu  = s * (1.f / 512.f);
    float var = s2 * (1.f / 512.f) - mu * mu;
    float r   = rsqrtf(var + EPSV);
    __half2* orow = (__half2*)(g_kvn + (size_t)row * DM);
    #pragma unroll
    for (int i = 0; i < 4; i++) {
        int k = lane + 32 * i;
        float4 gv = ((const float4*)gg)[k], bv = ((const float4*)bb)[k];
        float4 x = xv[i];
        orow[2 * k]     = __floats2half2_rn((x.x - mu) * r * gv.x + bv.x,
                                            (x.y - mu) * r * gv.y + bv.y);
        orow[2 * k + 1] = __floats2half2_rn((x.z - mu) * r * gv.z + bv.z,
                                            (x.w - mu) * r * gv.w + bv.w);
    }
}

// ===== 4) mma.sync GEMM: 128x128 CTA, 8 warps (32x64), 3-stage, fp16 acc + fp32 promote =====
// MODE 0: fused K/V projection (bx 0-3 -> K cols + head-LN -> fp16, 4-7 -> V cols fp16)
// MODE 1: O projection + latent residual (fp32 out)
#define AS_STRIDE 72                              // halfs per row (64 + 8 pad)
#define HALFS_A (128 * AS_STRIDE)                 // 9216
#define HALFS_STAGE (2 * HALFS_A)                 // 18432 (A tile + W tile)
#define STAGE_BYTES (HALFS_STAGE * 2)             // 36864
#define SMEM_GEMM_BYTES (3 * STAGE_BYTES)         // 110592

template <int MODE>
__global__ void __launch_bounds__(256, 2) mma_gemm(
    const __half* __restrict__ A,
    const __half* __restrict__ W0, const __half* __restrict__ W1,
    const float* __restrict__ bias0, const float* __restrict__ bias1,
    void* __restrict__ C0v, void* __restrict__ C1v,
    const float* __restrict__ lng, const float* __restrict__ lnb,
    const float* __restrict__ resid) {
    extern __shared__ __half hsm[];

    int tid = threadIdx.x;
    int bx = blockIdx.x, by = blockIdx.y;
    bool isK = (MODE == 0) ? (bx < 4) : false;
    int nb = (MODE == 0) ? (bx & 3) : bx;
    const __half* W   = (MODE == 0 && !isK) ? W1 : W0;
    const float* bias = (MODE == 0 && !isK) ? bias1 : bias0;
    int row0 = by * 128, col0 = nb * 128;
    const __half* Ab = A + (size_t)row0 * 512;
    const __half* Wb = W + (size_t)col0 * 512;

    int warp = tid >> 5, lane = tid & 31;
    int ln4 = lane >> 2, lnm = lane & 3;
    int wm = (warp & 3) * 32, wn = (warp >> 2) * 64;   // 8 warps: 4(m) x 2(n), 32x64 tiles

    uint32_t sbase = smem_u32(hsm);
    int fr = tid >> 3, fc = tid & 7;   // fill: base row (0..31), 16B col (0..7)

    // ldmatrix lane-dependent row/col offsets
    int mat = lane >> 3, lr = lane & 7;
    int aRow = (mat & 1) * 8 + lr;      // + wm + i*16
    int aKof = (mat >> 1) * 8;          // + s*16
    int bRow = (mat >> 1) * 8 + lr;     // + wn + jj*16
    int bKof = (mat & 1) * 8;           // + s*16

    float acc[2][8][4];                 // fp32 master accumulators
    #pragma unroll
    for (int i = 0; i < 2; i++)
        #pragma unroll
        for (int j = 0; j < 8; j++)
            #pragma unroll
            for (int e = 0; e < 4; e++) acc[i][j][e] = 0.f;
    uint32_t hacc[2][8][2];             // fp16 accumulators (promoted every 2 chunks)

    auto fill = [&](int c, int st) {   // chunk c into stage st
        uint32_t aB = sbase + (uint32_t)st * STAGE_BYTES;
        uint32_t wB = aB + HALFS_A * 2;
        int kb = c * 64;
        #pragma unroll
        for (int l = 0; l < 4; l++) {
            int r = fr + l * 32;
            cp_async16(aB + (uint32_t)(r * AS_STRIDE + fc * 8) * 2,
                       Ab + (size_t)r * 512 + kb + fc * 8);
            cp_async16(wB + (uint32_t)(r * AS_STRIDE + fc * 8) * 2,
                       Wb + (size_t)r * 512 + kb + fc * 8);
        }
    };

    fill(0, 0); CP_COMMIT();
    fill(1, 1); CP_COMMIT();

    int st = 0, stNext = 2;
    for (int c = 0; c < 8; c++) {
        if (c < 7) { CP_WAIT(1); } else { CP_WAIT(0); }
        __syncthreads();
        // Fill stage (c+2)%3 == stage read at iter c-1; top sync above guarantees
        // every warp finished iter c-1's MMAs, so overwrite is safe. NO second sync.
        if (c + 2 < 8) {
            fill(c + 2, stNext); CP_COMMIT();
            if (++stNext == 3) stNext = 0;
        }

        if ((c & 1) == 0) {     // start of a K=128 span: clear fp16 accumulators
            #pragma unroll
            for (int i = 0; i < 2; i++)
                #pragma unroll
                for (int j = 0; j < 8; j++) { hacc[i][j][0] = 0u; hacc[i][j][1] = 0u; }
        }

        uint32_t aBufAddr = sbase + (uint32_t)st * STAGE_BYTES;
        uint32_t wBufAddr = aBufAddr + HALFS_A * 2;

        #pragma unroll
        for (int s = 0; s < 4; s++) {   // k16 steps within chunk
            uint32_t a[2][4];
            #pragma unroll
            for (int i = 0; i < 2; i++) {
                uint32_t addr = aBufAddr +
                    (uint32_t)((wm + i * 16 + aRow) * AS_STRIDE + s * 16 + aKof) * 2;
                LDMX4(a[i][0], a[i][1], a[i][2], a[i][3], addr);
            }
            #pragma unroll
            for (int jj = 0; jj < 4; jj++) {
                uint32_t b0, b1, b2, b3;
                uint32_t addr = wBufAddr +
                    (uint32_t)((wn + jj * 16 + bRow) * AS_STRIDE + s * 16 + bKof) * 2;
                LDMX4(b0, b1, b2, b3, addr);
                MMA_F16H(hacc[0][2 * jj],     a[0], b0, b1);
                MMA_F16H(hacc[0][2 * jj + 1], a[0], b2, b3);
                MMA_F16H(hacc[1][2 * jj],     a[1], b0, b1);
                MMA_F16H(hacc[1][2 * jj + 1], a[1], b2, b3);
            }
        }

        if (c & 1) {            // end of a K=128 span: promote fp16 -> fp32
            #pragma unroll
            for (int i = 0; i < 2; i++)
                #pragma unroll
                for (int j = 0; j < 8; j++) {
                    float2 f0 = __half22float2(*reinterpret_cast<__half2*>(&hacc[i][j][0]));
                    float2 f1 = __half22float2(*reinterpret_cast<__half2*>(&hacc[i][j][1]));
                    acc[i][j][0] += f0.x; acc[i][j][1] += f0.y;
                    acc[i][j][2] += f1.x; acc[i][j][3] += f1.y;
                }
        }
        if (++st == 3) st = 0;
    }

    // ---- register-resident epilogue: bias (+head-LN | +residual), direct stores ----
    float2 b2[8];
    #pragma unroll
    for (int j = 0; j < 8; j++)
        b2[j] = *(const float2*)(bias + col0 + wn + j * 8 + 2 * lnm);
    float2 g2[8], be2[8];
    if (MODE == 0 && isK) {
        #pragma unroll
        for (int j = 0; j < 8; j++) {
            g2[j]  = *(const float2*)(lng + j * 8 + 2 * lnm);
            be2[j] = *(const float2*)(lnb + j * 8 + 2 * lnm);
        }
    }

    #pragma unroll
    for (int i = 0; i < 2; i++) {
        #pragma unroll
        for (int h = 0; h < 2; h++) {
            int row = row0 + wm + i * 16 + ln4 + 8 * h;
            float vx[8], vy[8];
            #pragma unroll
            for (int j = 0; j < 8; j++) {
                vx[j] = acc[i][j][2 * h]     + b2[j].x;
                vy[j] = acc[i][j][2 * h + 1] + b2[j].y;
            }
            if (MODE == 0) {
                if (isK) {
                    float s = 0.f, s2 = 0.f;
                    #pragma unroll
                    for (int j = 0; j < 8; j++) {
                        s  += vx[j] + vy[j];
                        s2 += vx[j] * vx[j] + vy[j] * vy[j];
                    }
                    s  += __shfl_xor_sync(0xffffffffu, s, 1);
                    s  += __shfl_xor_sync(0xffffffffu, s, 2);
                    s2 += __shfl_xor_sync(0xffffffffu, s2, 1);
                    s2 += __shfl_xor_sync(0xffffffffu, s2, 2);
                    float mu  = s * (1.f / 64.f);
                    float var = s2 * (1.f / 64.f) - mu * mu;
                    float rq  = rsqrtf(var + EPSV);
                    __half* cr = (__half*)C0v + (size_t)row * 512 + col0 + wn;
                    #pragma unroll
                    for (int j = 0; j < 8; j++) {
                        float ox = (vx[j] - mu) * rq * g2[j].x + be2[j].x;
                        float oy = (vy[j] - mu) * rq * g2[j].y + be2[j].y;
                        *(__half2*)(cr + j * 8 + 2 * lnm) = __floats2half2_rn(ox, oy);
                    }
                } else {
                    __half* cr = (__half*)C1v + (size_t)row * 512 + col0 + wn;
                    #pragma unroll
                    for (int j = 0; j < 8; j++)
                        *(__half2*)(cr + j * 8 + 2 * lnm) = __floats2half2_rn(vx[j], vy[j]);
                }
            } else {
                const float* rres = resid
                    + (size_t)(((row >> 11) << 3) + (row & 7)) * 512 + col0 + wn;
                #pragma unroll
                for (int j = 0; j < 8; j++) {
                    float2 rv = *(const float2*)(rres + j * 8 + 2 * lnm);
                    vx[j] += rv.x; vy[j] += rv.y;
                }
                float* cr = (float*)C0v + (size_t)row * 512 + col0 + wn;
                #pragma unroll
                for (int j = 0; j < 8; j++)
                    *(float2*)(cr + j * 8 + 2 * lnm) = make_float2(vx[j], vy[j]);
            }
        }
    }
}

// ---------------- 6) grouped attention: per (b,g), 8 heads x 8 q x 16 k ----------------
#define KS_STRIDE 514
#define SMEM_ATTN ((4096 + 16 * KS_STRIDE + 1024) * 4)

__global__ void __launch_bounds__(256) attn_kernel() {
    extern __shared__ float sm[];
    float* qs = sm;
    float* ks = sm + 4096;
    float* ps = sm + 4096 + 16 * KS_STRIDE;
    __shared__ int tok[16];

    int g = blockIdx.x, b = blockIdx.y;
    int tid = threadIdx.x;
    if (tid < 16) {
        int gr = g >> 4, gc = g & 15;
        tok[tid] = ((gr << 2) + (tid >> 2)) * 64 + (gc << 2) + (tid & 3);
    }
    __syncthreads();

    {
        const float4* src = (const float4*)(g_qh + (size_t)b * JL * DM);
        float4* dst = (float4*)qs;
        #pragma unroll
        for (int p = tid; p < 1024; p += 256) dst[p] = src[p];
    }
    // K rows: fp16 -> fp32 smem
    for (int p = tid; p < 16 * 256; p += 256) {
        int r = p >> 8, c2 = p & 255;
        __half2 hv = ((const __half2*)(g_k + ((size_t)(b * NSP + tok[r])) * DM))[c2];
        float2 f = __half22float2(hv);
        ks[r * KS_STRIDE + 2 * c2]     = f.x;
        ks[r * KS_STRIDE + 2 * c2 + 1] = f.y;
    }
    __syncthreads();

    int h = tid >> 5, lane = tid & 31;

    float pr[4];
    #pragma unroll
    for (int i = 0; i < 4; i++) {
        int p = lane + 32 * i;
        int q = p >> 4, k = p & 15;
        const float* qrow = qs + q * DM + h * DH;
        const float* krow = ks + k * KS_STRIDE + h * DH;
        float s = 0.f;
        #pragma unroll
        for (int d = 0; d < DH; d++) s += qrow[d] * krow[d];
        pr[i] = s * 0.125f;
    }
    #pragma unroll
    for (int i = 0; i < 4; i++) {
        float m = pr[i];
        #pragma unroll
        for (int o = 1; o < 16; o <<= 1) m = fmaxf(m, __shfl_xor_sync(0xffffffffu, m, o));
        float e = __expf(pr[i] - m);
        float ssum = e;
        #pragma unroll
        for (int o = 1; o < 16; o <<= 1) ssum += __shfl_xor_sync(0xffffffffu, ssum, o);
        pr[i] = e / ssum;
    }
    #pragma unroll
    for (int i = 0; i < 4; i++) ps[h * 128 + lane + 32 * i] = pr[i];
    __syncwarp();

    float v0[16], v1[16];
    #pragma unroll
    for (int k = 0; k < 16; k++) {
        const __half* vrow = g_v + ((size_t)(b * NSP + tok[k])) * DM + h * DH;
        v0[k] = __half2float(vrow[lane]);
        v1[k] = __half2float(vrow[lane + 32]);
    }
    #pragma unroll
    for (int q = 0; q < 8; q++) {
        float o0 = 0.f, o1 = 0.f;
        #pragma unroll
        for (int k = 0; k < 16; k++) {
            float pqk = ps[h * 128 + q * 16 + k];
            o0 += pqk * v0[k]; o1 += pqk * v1[k];
        }
        size_t base = ((size_t)(b * NLAT + g * JL + q)) * DM + h * DH;
        g_ao[base + lane]      = __float2half_rn(o0);
        g_ao[base + lane + 32] = __float2half_rn(o1);
    }
}

// ---------------- launch ----------------
extern "C" void kernel_launch(void* const* d_in, const int* in_sizes, int n_in,
                              void* d_out, int out_size) {
    const float* spatial = (const float*)d_in[0];
    const float* cond    = (const float*)d_in[1];
    const float* lt      = (const float*)d_in[2];
    const float* lp      = (const float*)d_in[3];
    const float* Wq      = (const float*)d_in[4];
    const float* bq      = (const float*)d_in[5];
    const float* Wk      = (const float*)d_in[6];
    const float* bk      = (const float*)d_in[7];
    const float* Wv      = (const float*)d_in[8];
    const float* bv      = (const float*)d_in[9];
    const float* Wo      = (const float*)d_in[10];
    const float* bo      = (const float*)d_in[11];
    const float* Wad     = (const float*)d_in[12];
    const float* bad     = (const float*)d_in[13];
    const float* qn_g    = (const float*)d_in[14];
    const float* qn_b    = (const float*)d_in[15];
    const float* kn_g    = (const float*)d_in[16];
    const float* kn_b    = (const float*)d_in[17];
    const float* nq_g    = (const float*)d_in[18];
    const float* nq_b    = (const float*)d_in[19];
    const float* nkv_g   = (const float*)d_in[20];
    const float* nkv_b   = (const float*)d_in[21];
    float* out = (float*)d_out;

    float *p_lat;
    __half *p_kvn, *p_k, *p_v, *p_ao, *p_wk, *p_wv, *p_wo;
    cudaGetSymbolAddress((void**)&p_kvn, g_kvn);
    cudaGetSymbolAddress((void**)&p_k,   g_k);
    cudaGetSymbolAddress((void**)&p_v,   g_v);
    cudaGetSymbolAddress((void**)&p_ao,  g_ao);
    cudaGetSymbolAddress((void**)&p_lat, g_lat);
    cudaGetSymbolAddress((void**)&p_wk,  g_wk);
    cudaGetSymbolAddress((void**)&p_wv,  g_wv);
    cudaGetSymbolAddress((void**)&p_wo,  g_wo);

    cudaFuncSetAttribute(mma_gemm<0>, cudaFuncAttributeMaxDynamicSharedMemorySize, SMEM_GEMM_BYTES);
    cudaFuncSetAttribute(mma_gemm<1>, cudaFuncAttributeMaxDynamicSharedMemorySize, SMEM_GEMM_BYTES);
    cudaFuncSetAttribute(attn_kernel, cudaFuncAttributeMaxDynamicSharedMemorySize, SMEM_ATTN);

    prelude_kernel<<<896, 256>>>(Wk, p_wk, Wv, p_wv, Wo, p_wo, cond, Wad, bad);
    latq_kernel<<<BATCH * JL, 512>>>(lt, lp, Wq, bq, nq_g, nq_b, qn_g, qn_b);
    lnkv_kernel<<<BATCH * NSP / 8, 256>>>(spatial, nkv_g, nkv_b);
    // fused K+V projection (128x128 tiles), head-LN on K in epilogue -> fp16 K, fp16 V
    mma_gemm<0><<<dim3(8, 128), 256, SMEM_GEMM_BYTES>>>(
        p_kvn, p_wk, p_wv, bk, bv, (void*)p_k, (void*)p_v, kn_g, kn_b, nullptr);
    attn_kernel<<<dim3(NG, BATCH), 256, SMEM_ATTN>>>();
    // O projection + residual (128x128 tiles), fp32 out
    mma_gemm<1><<<dim3(4, 64), 256, SMEM_GEMM_BYTES>>>(
        p_ao, p_wo, nullptr, bo, nullptr, (void*)out, nullptr, nullptr, nullptr, p_lat);
}

// round 12
// speedup vs baseline: 1.3462x; 1.3462x over previous
#include <cuda_runtime.h>
#include <cuda_fp16.h>
#include <math.h>
#include <stdint.h>

#define BATCH 4
#define NSP   4096      // H*W spatial tokens
#define DM    512
#define NH    8
#define DH    64
#define NG    256       // groups (16x16)
#define JL    8         // latents per group
#define NLAT  2048      // NG*JL
#define EPSV  1e-5f

// ---------------- helpers ----------------
#define MMA_F16(d, a, b) \
    asm volatile("mma.sync.aligned.m16n8k16.row.col.f32.f16.f16.f32 " \
        "{%0,%1,%2,%3}, {%4,%5,%6,%7}, {%8,%9}, {%0,%1,%2,%3};" \
        : "+f"((d)[0]), "+f"((d)[1]), "+f"((d)[2]), "+f"((d)[3]) \
        : "r"((a)[0]), "r"((a)[1]), "r"((a)[2]), "r"((a)[3]), \
          "r"((b)[0]), "r"((b)[1]))

#define LDMX4(r0, r1, r2, r3, addr) \
    asm volatile("ldmatrix.sync.aligned.m8n8.x4.shared.b16 {%0,%1,%2,%3}, [%4];" \
        : "=r"(r0), "=r"(r1), "=r"(r2), "=r"(r3) : "r"(addr))

__device__ __forceinline__ void cp_async16(uint32_t smem_addr, const void* gptr) {
    asm volatile("cp.async.cg.shared.global [%0], [%1], 16;"
        :: "r"(smem_addr), "l"(gptr));
}
#define CP_COMMIT()  asm volatile("cp.async.commit_group;" ::: "memory")
#define CP_WAIT(N)   asm volatile("cp.async.wait_group %0;" :: "n"(N) : "memory")

__device__ __forceinline__ uint32_t smem_u32(const void* p) {
    uint32_t a;
    asm("{ .reg .u64 t; cvta.to.shared.u64 t, %1; cvt.u32.u64 %0, t; }" : "=r"(a) : "l"(p));
    return a;
}

// ---------------- scratch (device globals; no allocs allowed) ----------------
__device__ float  g_mod[BATCH * 1024];
__device__ float  g_lat[BATCH * JL * DM];       // modulated latents (residual, fp32)
__device__ float  g_qh [BATCH * JL * DM];       // q heads post head-LN (fp32)
__device__ __half g_kvn[BATCH * NSP * DM];      // LN(spatial), fp16
__device__ __half g_k  [BATCH * NSP * DM];      // k proj, head-LN fused, fp16
__device__ __half g_v  [BATCH * NSP * DM];      // v proj, fp16
__device__ __half g_ao [BATCH * NLAT * DM];     // attention out, fp16
__device__ __half g_wk [DM * DM];               // fp16 weights
__device__ __half g_wv [DM * DM];
__device__ __half g_wo [DM * DM];

// ==== 1) stage1: wcvt (blocks 0-767) + mod GEMV (768-895) + lnkv (896-2943) ====
__global__ void __launch_bounds__(256) stage1_kernel(
    const float* __restrict__ s0, __half* __restrict__ d0,
    const float* __restrict__ s1, __half* __restrict__ d1,
    const float* __restrict__ s2, __half* __restrict__ d2,
    const float* __restrict__ cond,
    const float* __restrict__ Wad,
    const float* __restrict__ bad,
    const float* __restrict__ sp,
    const float* __restrict__ gg,
    const float* __restrict__ bb) {
    int blk = blockIdx.x;
    int t = threadIdx.x;
    if (blk < 768) {
        int which = blk >> 8;
        int i = (blk & 255) * 256 + t;       // float4 index
        const float* src = (which == 0) ? s0 : (which == 1) ? s1 : s2;
        __half*      dst = (which == 0) ? d0 : (which == 1) ? d1 : d2;
        float4 v = ((const float4*)src)[i];
        ((__half2*)dst)[2 * i]     = __floats2half2_rn(v.x, v.y);
        ((__half2*)dst)[2 * i + 1] = __floats2half2_rn(v.z, v.w);
    } else if (blk < 896) {
        int o = (blk - 768) * 32 + (t >> 3);  // 0..4095
        int sub = t & 7;
        int b = o >> 10, oo = o & 1023;
        const float4* w  = (const float4*)(Wad + (size_t)oo * 512);
        const float4* cn = (const float4*)(cond + (size_t)b * 512);
        float acc = 0.f;
        #pragma unroll
        for (int k = sub * 16; k < sub * 16 + 16; k++) {
            float4 wv = w[k], cv = cn[k];
            acc += wv.x * cv.x + wv.y * cv.y + wv.z * cv.z + wv.w * cv.w;
        }
        acc += __shfl_xor_sync(0xffffffffu, acc, 1);
        acc += __shfl_xor_sync(0xffffffffu, acc, 2);
        acc += __shfl_xor_sync(0xffffffffu, acc, 4);
        if (sub == 0) g_mod[b * 1024 + oo] = acc + bad[oo];
    } else {
        // lnkv: warp-per-row
        int warp = t >> 5, lane = t & 31;
        int row = (blk - 896) * 8 + warp;
        const float4* x4 = (const float4*)(sp + (size_t)row * DM);
        float4 xv[4];
        float s = 0.f, s2 = 0.f;
        #pragma unroll
        for (int i = 0; i < 4; i++) {
            float4 x = x4[lane + 32 * i];
            xv[i] = x;
            s  += x.x + x.y + x.z + x.w;
            s2 += x.x * x.x + x.y * x.y + x.z * x.z + x.w * x.w;
        }
        #pragma unroll
        for (int o = 16; o >= 1; o >>= 1) {
            s  += __shfl_xor_sync(0xffffffffu, s,  o);
            s2 += __shfl_xor_sync(0xffffffffu, s2, o);
        }
        float mu  = s * (1.f / 512.f);
        float var = s2 * (1.f / 512.f) - mu * mu;
        float r   = rsqrtf(var + EPSV);
        __half2* orow = (__half2*)(g_kvn + (size_t)row * DM);
        #pragma unroll
        for (int i = 0; i < 4; i++) {
            int k = lane + 32 * i;
            float4 gv = ((const float4*)gg)[k], bv = ((const float4*)bb)[k];
            float4 x = xv[i];
            orow[2 * k]     = __floats2half2_rn((x.x - mu) * r * gv.x + bv.x,
                                                (x.y - mu) * r * gv.y + bv.y);
            orow[2 * k + 1] = __floats2half2_rn((x.z - mu) * r * gv.z + bv.z,
                                                (x.w - mu) * r * gv.w + bv.w);
        }
    }
}

// ===== 4) fp16 mma.sync GEMM: 128x128 CTA, 8 warps (32x64), 3-stage, ONE sync/chunk =====
// MODE 0: grid (9,128): bx 0-3 K cols (+head-LN, fp16 out), bx 4-7 V cols (fp16 out),
//         bx==8 && by<32: embedded latq (latents pipeline, 256 threads)
// MODE 1: O projection + latent residual (fp32 out), grid (4,64)
#define AS_STRIDE 72                              // halfs per row (64 + 8 pad)
#define HALFS_A (128 * AS_STRIDE)                 // 9216
#define HALFS_STAGE (2 * HALFS_A)                 // 18432 (A tile + W tile)
#define STAGE_BYTES (HALFS_STAGE * 2)             // 36864
#define SMEM_GEMM_BYTES (3 * STAGE_BYTES)         // 110592

template <int MODE>
__global__ void __launch_bounds__(256, 2) mma_gemm(
    const __half* __restrict__ A,
    const __half* __restrict__ W0, const __half* __restrict__ W1,
    const float* __restrict__ bias0, const float* __restrict__ bias1,
    void* __restrict__ C0v, void* __restrict__ C1v,
    const float* __restrict__ lng, const float* __restrict__ lnb,
    const float* __restrict__ resid,
    const float* __restrict__ lt, const float* __restrict__ lp,
    const float* __restrict__ Wq, const float* __restrict__ bq,
    const float* __restrict__ nqg, const float* __restrict__ nqb,
    const float* __restrict__ qng, const float* __restrict__ qnb) {
    extern __shared__ __half hsm[];

    int tid = threadIdx.x;
    int bx = blockIdx.x, by = blockIdx.y;

    if (MODE == 0 && bx == 8) {
        // ---------------- embedded latq: block (8, by), by<32 ----------------
        if (by >= 32) return;
        float* sval = (float*)hsm;            // 512
        float* racc = sval + 512;             // 512
        float* wred = racc + 512;             // 8 warp partials x2
        float* hstat = wred + 16;             // 8 heads x2 (mu, rs)
        int b = by >> 3, j = by & 7;
        int t = tid;                          // 0..255, cols t and t+256
        int warp = t >> 5, lane = t & 31;

        float la[2];
        #pragma unroll
        for (int hh = 0; hh < 2; hh++) {
            int c = t + hh * 256;
            float base  = lt[j * DM + c] + lp[j * DM + c];
            float shift = g_mod[b * 1024 + c];
            float scale = g_mod[b * 1024 + 512 + c];
            la[hh] = base * (1.f + scale) + shift;
            g_lat[(size_t)by * DM + c] = la[hh];
        }
        float s = la[0] + la[1];
        float s2 = la[0] * la[0] + la[1] * la[1];
        #pragma unroll
        for (int o = 16; o >= 1; o >>= 1) {
            s  += __shfl_xor_sync(0xffffffffu, s,  o);
            s2 += __shfl_xor_sync(0xffffffffu, s2, o);
        }
        if (lane == 0) { wred[warp] = s; wred[8 + warp] = s2; }
        __syncthreads();
        s = 0.f; s2 = 0.f;
        #pragma unroll
        for (int w = 0; w < 8; w++) { s += wred[w]; s2 += wred[8 + w]; }
        float mu  = s * (1.f / 512.f);
        float var = s2 * (1.f / 512.f) - mu * mu;
        float rs  = rsqrtf(var + EPSV);
        #pragma unroll
        for (int hh = 0; hh < 2; hh++) {
            int c = t + hh * 256;
            sval[c] = (la[hh] - mu) * rs * nqg[c] + nqb[c];
        }
        __syncthreads();

        float acc2[2];
        #pragma unroll
        for (int hh = 0; hh < 2; hh++) {
            int c = t + hh * 256;
            float acc = bq[c];
            const float4* w4 = (const float4*)(Wq + (size_t)c * DM);
            const float4* s4 = (const float4*)sval;
            #pragma unroll 8
            for (int k = 0; k < 128; k++) {
                float4 wv = w4[k], sv = s4[k];
                acc += wv.x * sv.x + wv.y * sv.y + wv.z * sv.z + wv.w * sv.w;
            }
            acc2[hh] = acc;
            racc[c] = acc;
        }
        __syncthreads();
        // head-LN: warp w reduces head w (64 cols)
        {
            float v0 = racc[warp * 64 + lane], v1 = racc[warp * 64 + 32 + lane];
            float hs = v0 + v1, hs2 = v0 * v0 + v1 * v1;
            #pragma unroll
            for (int o = 16; o >= 1; o >>= 1) {
                hs  += __shfl_xor_sync(0xffffffffu, hs,  o);
                hs2 += __shfl_xor_sync(0xffffffffu, hs2, o);
            }
            if (lane == 0) {
                float hmu = hs * (1.f / 64.f);
                float hvar = hs2 * (1.f / 64.f) - hmu * hmu;
                hstat[warp] = hmu;
                hstat[8 + warp] = rsqrtf(hvar + EPSV);
            }
        }
        __syncthreads();
        #pragma unroll
        for (int hh = 0; hh < 2; hh++) {
            int c = t + hh * 256;
            int h = c >> 6, l = c & 63;
            g_qh[(size_t)by * DM + c] =
                (acc2[hh] - hstat[h]) * hstat[8 + h] * qng[l] + qnb[l];
        }
        return;
    }

    bool isK = (MODE == 0) ? (bx < 4) : false;
    int nb = (MODE == 0) ? (bx & 3) : bx;
    const __half* W   = (MODE == 0 && !isK) ? W1 : W0;
    const float* bias = (MODE == 0 && !isK) ? bias1 : bias0;
    int row0 = by * 128, col0 = nb * 128;
    const __half* Ab = A + (size_t)row0 * 512;
    const __half* Wb = W + (size_t)col0 * 512;

    int warp = tid >> 5, lane = tid & 31;
    int ln4 = lane >> 2, lnm = lane & 3;
    int wm = (warp & 3) * 32, wn = (warp >> 2) * 64;   // 8 warps: 4(m) x 2(n), 32x64 tiles

    uint32_t sbase = smem_u32(hsm);
    int fr = tid >> 3, fc = tid & 7;   // fill: base row (0..31), 16B col (0..7)

    // ldmatrix lane-dependent row/col offsets
    int mat = lane >> 3, lr = lane & 7;
    int aRow = (mat & 1) * 8 + lr;      // + wm + i*16
    int aKof = (mat >> 1) * 8;          // + s*16
    int bRow = (mat >> 1) * 8 + lr;     // + wn + jj*16
    int bKof = (mat & 1) * 8;           // + s*16

    float acc[2][8][4];
    #pragma unroll
    for (int i = 0; i < 2; i++)
        #pragma unroll
        for (int j = 0; j < 8; j++)
            #pragma unroll
            for (int e = 0; e < 4; e++) acc[i][j][e] = 0.f;

    auto fill = [&](int c, int st) {   // chunk c into stage st
        uint32_t aB = sbase + (uint32_t)st * STAGE_BYTES;
        uint32_t wB = aB + HALFS_A * 2;
        int kb = c * 64;
        #pragma unroll
        for (int l = 0; l < 4; l++) {
            int r = fr + l * 32;
            cp_async16(aB + (uint32_t)(r * AS_STRIDE + fc * 8) * 2,
                       Ab + (size_t)r * 512 + kb + fc * 8);
            cp_async16(wB + (uint32_t)(r * AS_STRIDE + fc * 8) * 2,
                       Wb + (size_t)r * 512 + kb + fc * 8);
        }
    };

    fill(0, 0); CP_COMMIT();
    fill(1, 1); CP_COMMIT();

    int st = 0, stNext = 2;
    for (int c = 0; c < 8; c++) {
        if (c < 7) { CP_WAIT(1); } else { CP_WAIT(0); }
        __syncthreads();
        // Fill stage (c+2)%3 == stage read at iter c-1; top sync above guarantees
        // every warp finished iter c-1's MMAs, so overwrite is safe. NO second sync.
        if (c + 2 < 8) {
            fill(c + 2, stNext); CP_COMMIT();
            if (++stNext == 3) stNext = 0;
        }

        uint32_t aBufAddr = sbase + (uint32_t)st * STAGE_BYTES;
        uint32_t wBufAddr = aBufAddr + HALFS_A * 2;

        #pragma unroll
        for (int s = 0; s < 4; s++) {   // k16 steps within chunk
            uint32_t a[2][4], bfr[8][2];
            #pragma unroll
            for (int i = 0; i < 2; i++) {
                uint32_t addr = aBufAddr +
                    (uint32_t)((wm + i * 16 + aRow) * AS_STRIDE + s * 16 + aKof) * 2;
                LDMX4(a[i][0], a[i][1], a[i][2], a[i][3], addr);
            }
            #pragma unroll
            for (int jj = 0; jj < 4; jj++) {
                uint32_t addr = wBufAddr +
                    (uint32_t)((wn + jj * 16 + bRow) * AS_STRIDE + s * 16 + bKof) * 2;
                LDMX4(bfr[2 * jj][0], bfr[2 * jj][1],
                      bfr[2 * jj + 1][0], bfr[2 * jj + 1][1], addr);
            }
            #pragma unroll
            for (int i = 0; i < 2; i++)
                #pragma unroll
                for (int j = 0; j < 8; j++)
                    MMA_F16(acc[i][j], a[i], bfr[j]);
        }
        if (++st == 3) st = 0;
    }

    // ---- register-resident epilogue: bias (+head-LN | +residual), direct stores ----
    float2 b2[8];
    #pragma unroll
    for (int j = 0; j < 8; j++)
        b2[j] = *(const float2*)(bias + col0 + wn + j * 8 + 2 * lnm);
    float2 g2[8], be2[8];
    if (MODE == 0 && isK) {
        #pragma unroll
        for (int j = 0; j < 8; j++) {
            g2[j]  = *(const float2*)(lng + j * 8 + 2 * lnm);
            be2[j] = *(const float2*)(lnb + j * 8 + 2 * lnm);
        }
    }

    #pragma unroll
    for (int i = 0; i < 2; i++) {
        #pragma unroll
        for (int h = 0; h < 2; h++) {
            int row = row0 + wm + i * 16 + ln4 + 8 * h;
            float vx[8], vy[8];
            #pragma unroll
            for (int j = 0; j < 8; j++) {
                vx[j] = acc[i][j][2 * h]     + b2[j].x;
                vy[j] = acc[i][j][2 * h + 1] + b2[j].y;
            }
            if (MODE == 0) {
                if (isK) {
                    float s = 0.f, s2 = 0.f;
                    #pragma unroll
                    for (int j = 0; j < 8; j++) {
                        s  += vx[j] + vy[j];
                        s2 += vx[j] * vx[j] + vy[j] * vy[j];
                    }
                    s  += __shfl_xor_sync(0xffffffffu, s, 1);
                    s  += __shfl_xor_sync(0xffffffffu, s, 2);
                    s2 += __shfl_xor_sync(0xffffffffu, s2, 1);
                    s2 += __shfl_xor_sync(0xffffffffu, s2, 2);
                    float mu  = s * (1.f / 64.f);
                    float var = s2 * (1.f / 64.f) - mu * mu;
                    float rq  = rsqrtf(var + EPSV);
                    __half* cr = (__half*)C0v + (size_t)row * 512 + col0 + wn;
                    #pragma unroll
                    for (int j = 0; j < 8; j++) {
                        float ox = (vx[j] - mu) * rq * g2[j].x + be2[j].x;
                        float oy = (vy[j] - mu) * rq * g2[j].y + be2[j].y;
                        *(__half2*)(cr + j * 8 + 2 * lnm) = __floats2half2_rn(ox, oy);
                    }
                } else {
                    __half* cr = (__half*)C1v + (size_t)row * 512 + col0 + wn;
                    #pragma unroll
                    for (int j = 0; j < 8; j++)
                        *(__half2*)(cr + j * 8 + 2 * lnm) = __floats2half2_rn(vx[j], vy[j]);
                }
            } else {
                const float* rres = resid
                    + (size_t)(((row >> 11) << 3) + (row & 7)) * 512 + col0 + wn;
                #pragma unroll
                for (int j = 0; j < 8; j++) {
                    float2 rv = *(const float2*)(rres + j * 8 + 2 * lnm);
                    vx[j] += rv.x; vy[j] += rv.y;
                }
                float* cr = (float*)C0v + (size_t)row * 512 + col0 + wn;
                #pragma unroll
                for (int j = 0; j < 8; j++)
                    *(float2*)(cr + j * 8 + 2 * lnm) = make_float2(vx[j], vy[j]);
            }
        }
    }
}

// ---------------- 6) grouped attention: per (b,g), 8 heads x 8 q x 16 k ----------------
#define KS_STRIDE 514
#define SMEM_ATTN ((4096 + 16 * KS_STRIDE + 1024) * 4)

__global__ void __launch_bounds__(256) attn_kernel() {
    extern __shared__ float sm[];
    float* qs = sm;
    float* ks = sm + 4096;
    float* ps = sm + 4096 + 16 * KS_STRIDE;
    __shared__ int tok[16];

    int g = blockIdx.x, b = blockIdx.y;
    int tid = threadIdx.x;
    if (tid < 16) {
        int gr = g >> 4, gc = g & 15;
        tok[tid] = ((gr << 2) + (tid >> 2)) * 64 + (gc << 2) + (tid & 3);
    }
    __syncthreads();

    {
        const float4* src = (const float4*)(g_qh + (size_t)b * JL * DM);
        float4* dst = (float4*)qs;
        #pragma unroll
        for (int p = tid; p < 1024; p += 256) dst[p] = src[p];
    }
    // K rows: fp16 -> fp32 smem
    for (int p = tid; p < 16 * 256; p += 256) {
        int r = p >> 8, c2 = p & 255;
        __half2 hv = ((const __half2*)(g_k + ((size_t)(b * NSP + tok[r])) * DM))[c2];
        float2 f = __half22float2(hv);
        ks[r * KS_STRIDE + 2 * c2]     = f.x;
        ks[r * KS_STRIDE + 2 * c2 + 1] = f.y;
    }
    __syncthreads();

    int h = tid >> 5, lane = tid & 31;

    float pr[4];
    #pragma unroll
    for (int i = 0; i < 4; i++) {
        int p = lane + 32 * i;
        int q = p >> 4, k = p & 15;
        const float* qrow = qs + q * DM + h * DH;
        const float* krow = ks + k * KS_STRIDE + h * DH;
        float s = 0.f;
        #pragma unroll
        for (int d = 0; d < DH; d++) s += qrow[d] * krow[d];
        pr[i] = s * 0.125f;
    }
    #pragma unroll
    for (int i = 0; i < 4; i++) {
        float m = pr[i];
        #pragma unroll
        for (int o = 1; o < 16; o <<= 1) m = fmaxf(m, __shfl_xor_sync(0xffffffffu, m, o));
        float e = __expf(pr[i] - m);
        float ssum = e;
        #pragma unroll
        for (int o = 1; o < 16; o <<= 1) ssum += __shfl_xor_sync(0xffffffffu, ssum, o);
        pr[i] = e / ssum;
    }
    #pragma unroll
    for (int i = 0; i < 4; i++) ps[h * 128 + lane + 32 * i] = pr[i];
    __syncwarp();

    float v0[16], v1[16];
    #pragma unroll
    for (int k = 0; k < 16; k++) {
        const __half* vrow = g_v + ((size_t)(b * NSP + tok[k])) * DM + h * DH;
        v0[k] = __half2float(vrow[lane]);
        v1[k] = __half2float(vrow[lane + 32]);
    }
    #pragma unroll
    for (int q = 0; q < 8; q++) {
        float o0 = 0.f, o1 = 0.f;
        #pragma unroll
        for (int k = 0; k < 16; k++) {
            float pqk = ps[h * 128 + q * 16 + k];
            o0 += pqk * v0[k]; o1 += pqk * v1[k];
        }
        size_t base = ((size_t)(b * NLAT + g * JL + q)) * DM + h * DH;
        g_ao[base + lane]      = __float2half_rn(o0);
        g_ao[base + lane + 32] = __float2half_rn(o1);
    }
}

// ---------------- launch ----------------
extern "C" void kernel_launch(void* const* d_in, const int* in_sizes, int n_in,
                              void* d_out, int out_size) {
    const float* spatial = (const float*)d_in[0];
    const float* cond    = (const float*)d_in[1];
    const float* lt      = (const float*)d_in[2];
    const float* lp      = (const float*)d_in[3];
    const float* Wq      = (const float*)d_in[4];
    const float* bq      = (const float*)d_in[5];
    const float* Wk      = (const float*)d_in[6];
    const float* bk      = (const float*)d_in[7];
    const float* Wv      = (const float*)d_in[8];
    const float* bv      = (const float*)d_in[9];
    const float* Wo      = (const float*)d_in[10];
    const float* bo      = (const float*)d_in[11];
    const float* Wad     = (const float*)d_in[12];
    const float* bad     = (const float*)d_in[13];
    const float* qn_g    = (const float*)d_in[14];
    const float* qn_b    = (const float*)d_in[15];
    const float* kn_g    = (const float*)d_in[16];
    const float* kn_b    = (const float*)d_in[17];
    const float* nq_g    = (const float*)d_in[18];
    const float* nq_b    = (const float*)d_in[19];
    const float* nkv_g   = (const float*)d_in[20];
    const float* nkv_b   = (const float*)d_in[21];
    float* out = (float*)d_out;

    float *p_lat;
    __half *p_kvn, *p_k, *p_v, *p_ao, *p_wk, *p_wv, *p_wo;
    cudaGetSymbolAddress((void**)&p_kvn, g_kvn);
    cudaGetSymbolAddress((void**)&p_k,   g_k);
    cudaGetSymbolAddress((void**)&p_v,   g_v);
    cudaGetSymbolAddress((void**)&p_ao,  g_ao);
    cudaGetSymbolAddress((void**)&p_lat, g_lat);
    cudaGetSymbolAddress((void**)&p_wk,  g_wk);
    cudaGetSymbolAddress((void**)&p_wv,  g_wv);
    cudaGetSymbolAddress((void**)&p_wo,  g_wo);

    cudaFuncSetAttribute(mma_gemm<0>, cudaFuncAttributeMaxDynamicSharedMemorySize, SMEM_GEMM_BYTES);
    cudaFuncSetAttribute(mma_gemm<1>, cudaFuncAttributeMaxDynamicSharedMemorySize, SMEM_GEMM_BYTES);
    cudaFuncSetAttribute(attn_kernel, cudaFuncAttributeMaxDynamicSharedMemorySize, SMEM_ATTN);

    // stage1: weight cvt + mod GEMV + lnkv, one launch (2944 blocks)
    stage1_kernel<<<2944, 256>>>(Wk, p_wk, Wv, p_wv, Wo, p_wo,
                                 cond, Wad, bad, spatial, nkv_g, nkv_b);
    // fused K+V projection + embedded latq (bx==8, by<32)
    mma_gemm<0><<<dim3(9, 128), 256, SMEM_GEMM_BYTES>>>(
        p_kvn, p_wk, p_wv, bk, bv, (void*)p_k, (void*)p_v, kn_g, kn_b, nullptr,
        lt, lp, Wq, bq, nq_g, nq_b, qn_g, qn_b);
    attn_kernel<<<dim3(NG, BATCH), 256, SMEM_ATTN>>>();
    // O projection + residual (fp32 out)
    mma_gemm<1><<<dim3(4, 64), 256, SMEM_GEMM_BYTES>>>(
        p_ao, p_wo, nullptr, bo, nullptr, (void*)out, nullptr, nullptr, nullptr, p_lat,
        nullptr, nullptr, nullptr, nullptr, nullptr, nullptr, nullptr, nullptr);
}